// round 1
// baseline (speedup 1.0000x reference)
#include <cuda_runtime.h>

// ---------------- problem constants ----------------
#define NCB   9
#define BB    16
#define DD    512
#define TT    4096
#define KK    1024
#define CDIM  8

#define TILE     64     // positions per CTA
#define THREADS  512
#define RSTRIDE  65     // residual row stride (floats), conflict-free

// output layout (concatenated, float32)
#define ZQ_OFF     0ll
#define CODES_OFF  33554432ll                 // 16*512*4096
#define LAT_OFF    34144256ll                 // + 16*9*4096
#define LOSS_OFF   38862848ll                 // + 16*72*4096

// ---------------- smem layout (float offsets) ----------------
#define S_R      0          // 512*65 = 33280
#define S_WI     33280      // 8*512  = 4096   [c][d]
#define S_WO     37376      // 8*512  = 4096   [c][d] (transposed)
#define S_CBN    41472      // 1024*8 = 8192
#define S_C2     49664      // 1024
#define S_BIN    50688      // 8
#define S_BOUT   50696      // 512
#define S_ZE     51208      // 64*9 = 576 (stride 9)
#define S_CBQ    51784      // 576
#define S_BESTD  52360      // 8*64 = 512
#define S_BESTI  52872      // 512 (int)
#define S_LOSS   53384      // 64 doubles = 128 floats (byte off 213536, 8-aligned)
#define SMEM_FLOATS 53512
#define SMEM_BYTES  (SMEM_FLOATS * 4)   // 214048

// ---------------- device scratch (no allocation allowed) ----------------
__device__ float  g_cbn[NCB * KK * CDIM];
__device__ float  g_c2 [NCB * KK];
__device__ double g_loss;

// ---------------- prep: normalize codebooks, zero loss ----------------
__global__ void rvq_prep(const float* __restrict__ cb) {
    int v = blockIdx.x * blockDim.x + threadIdx.x;
    if (v == 0) g_loss = 0.0;
    if (v >= NCB * KK) return;
    const float* src = cb + (size_t)v * CDIM;
    float x[CDIM];
#pragma unroll
    for (int c = 0; c < CDIM; c++) x[c] = src[c];
    float ss = 0.f;
#pragma unroll
    for (int c = 0; c < CDIM; c++) ss = fmaf(x[c], x[c], ss);
    float nrm = __fsqrt_rn(ss);
    float den = fmaxf(nrm, 1e-12f);
    float c2 = 0.f;
#pragma unroll
    for (int c = 0; c < CDIM; c++) {
        float e = __fdiv_rn(x[c], den);     // matches reference x / max(||x||, eps)
        g_cbn[(size_t)v * CDIM + c] = e;
        c2 = fmaf(e, e, c2);
    }
    g_c2[v] = c2;
}

// ---------------- main fused RVQ kernel ----------------
extern __shared__ float sm[];

__global__ void __launch_bounds__(THREADS, 1)
rvq_main(const float* __restrict__ z,
         const float* __restrict__ w_in,
         const float* __restrict__ b_in,
         const float* __restrict__ w_out,
         const float* __restrict__ b_out,
         const float* __restrict__ cbraw,
         float* __restrict__ out) {
    const int tid  = threadIdx.x;
    const int pos0 = blockIdx.x * TILE;
    const int b    = pos0 >> 12;          // pos0 / 4096
    const int t0   = pos0 & (TT - 1);

    const float* zb = z + ((size_t)b * DD) * TT + t0;

    // load residual columns: r[d][toff], coalesced global, conflict-free smem
    for (int idx = tid; idx < DD * TILE; idx += THREADS) {
        int d = idx >> 6, to = idx & 63;
        sm[S_R + d * RSTRIDE + to] = zb[(size_t)d * TT + to];
    }

    double lossAcc = 0.0;

    for (int i = 0; i < NCB; ++i) {
        __syncthreads();    // prev-iteration Phase C done before weight overwrite / r reads

        // ---- stage per-codebook weights into smem ----
        const float* wi = w_in  + (size_t)i * CDIM * DD;   // [c][d]
        const float* wo = w_out + (size_t)i * DD * CDIM;   // [d][c] -> transpose to [c][d]
        for (int idx = tid; idx < CDIM * DD; idx += THREADS) {
            sm[S_WI + idx] = wi[idx];
            sm[S_WO + (idx & 7) * DD + (idx >> 3)] = wo[idx];
        }
        for (int idx = tid; idx < KK * CDIM; idx += THREADS)
            sm[S_CBN + idx] = g_cbn[(size_t)i * KK * CDIM + idx];
        for (int idx = tid; idx < KK; idx += THREADS)
            sm[S_C2 + idx] = g_c2[(size_t)i * KK + idx];
        if (tid < CDIM) sm[S_BIN + tid] = b_in[(size_t)i * CDIM + tid];
        sm[S_BOUT + tid] = (tid < DD) ? b_out[(size_t)i * DD + tid] : 0.f;
        __syncthreads();

        // ---- Phase A: z_e[p][c] = w_in[c,:] . r[:,p] + b_in[c] ----
        {
            int p = tid & 63, c = tid >> 6;          // warp lanes: distinct p, uniform c
            const float* wrow = sm + S_WI + c * DD;
            const float* rp   = sm + S_R + p;
            float a0 = 0.f, a1 = 0.f, a2 = 0.f, a3 = 0.f;
#pragma unroll 8
            for (int d = 0; d < DD; d += 4) {
                float4 w4 = *reinterpret_cast<const float4*>(wrow + d);  // uniform bcast
                a0 = fmaf(rp[(d    ) * RSTRIDE], w4.x, a0);
                a1 = fmaf(rp[(d + 1) * RSTRIDE], w4.y, a1);
                a2 = fmaf(rp[(d + 2) * RSTRIDE], w4.z, a2);
                a3 = fmaf(rp[(d + 3) * RSTRIDE], w4.w, a3);
            }
            sm[S_ZE + p * 9 + c] = ((a0 + a1) + (a2 + a3)) + sm[S_BIN + c];
        }
        __syncthreads();

        // ---- Phase B: per-position argmin over 1024 codes (8 k-slices) ----
        {
            int p = tid & 63, slice = tid >> 6;
            float zev[8], en[8];
#pragma unroll
            for (int c = 0; c < 8; c++) zev[c] = sm[S_ZE + p * 9 + c];
            float ss = 0.f;
#pragma unroll
            for (int c = 0; c < 8; c++) ss = fmaf(zev[c], zev[c], ss);
            float den = fmaxf(__fsqrt_rn(ss), 1e-12f);
#pragma unroll
            for (int c = 0; c < 8; c++) en[c] = __fdiv_rn(zev[c], den);
            float en2 = 0.f;
#pragma unroll
            for (int c = 0; c < 8; c++) en2 = fmaf(en[c], en[c], en2);

            float best = 3.402823466e38f;
            int   bi   = 0;
            const int k0 = slice << 7;               // 128 codes per slice
            const float4* cb4 = reinterpret_cast<const float4*>(sm + S_CBN) + (k0 << 1);
            const float*  c2p = sm + S_C2 + k0;
#pragma unroll 4
            for (int j = 0; j < 128; ++j) {
                float4 cA = cb4[2 * j];              // uniform bcast LDS.128
                float4 cB = cb4[2 * j + 1];
                float dot = en[0] * cA.x;
                dot = fmaf(en[1], cA.y, dot); dot = fmaf(en[2], cA.z, dot);
                dot = fmaf(en[3], cA.w, dot); dot = fmaf(en[4], cB.x, dot);
                dot = fmaf(en[5], cB.y, dot); dot = fmaf(en[6], cB.z, dot);
                dot = fmaf(en[7], cB.w, dot);
                float dist = fmaf(-2.f, dot, en2) + c2p[j];   // (en2 - 2*dot) + c2, exact
                if (dist < best) { best = dist; bi = k0 + j; } // strict: first-min wins
            }
            sm[S_BESTD + (slice << 6) + p] = best;
            reinterpret_cast<int*>(sm + S_BESTI)[(slice << 6) + p] = bi;
        }
        __syncthreads();

        // ---- combine slices, emit codes/latents, gather raw codebook, loss ----
        {
            int p = tid & 63, c = tid >> 6;
            // latents[b][i*8+c][t0+p] = raw z_e (coalesced over p)
            out[LAT_OFF + ((size_t)(b * (NCB * CDIM) + i * CDIM + c)) * TT + t0 + p] =
                sm[S_ZE + p * 9 + c];

            if (tid < 64) {
                int pp = tid;
                float best = sm[S_BESTD + pp];
                int   bi   = reinterpret_cast<int*>(sm + S_BESTI)[pp];
#pragma unroll
                for (int s = 1; s < 8; s++) {        // ascending k ranges: ties keep lowest k
                    float d2 = sm[S_BESTD + (s << 6) + pp];
                    int   i2 = reinterpret_cast<int*>(sm + S_BESTI)[(s << 6) + pp];
                    if (d2 < best) { best = d2; bi = i2; }
                }
                out[CODES_OFF + ((size_t)(b * NCB + i)) * TT + t0 + pp] = (float)bi;

                const float* cr = cbraw + ((size_t)i * KK + bi) * CDIM;  // RAW codebook
                double ls = 0.0;
#pragma unroll
                for (int cc = 0; cc < 8; cc++) {
                    float cv = __ldg(cr + cc);
                    sm[S_CBQ + pp * 9 + cc] = cv;
                    float df = sm[S_ZE + pp * 9 + cc] - cv;
                    ls += (double)(df * df);
                }
                lossAcc += ls;
            }
        }
        __syncthreads();

        // ---- Phase C: r[:,p] -= w_out @ cbq[p] + b_out ----
        {
            int p = tid & 63, slice = tid >> 6;
            int d0 = slice << 6;                     // 64 d per thread
            float q[8];
#pragma unroll
            for (int c = 0; c < 8; c++) q[c] = sm[S_CBQ + p * 9 + c];
            float* rp = sm + S_R + p;
#pragma unroll 4
            for (int d = d0; d < d0 + 64; ++d) {
                float acc = q[0] * sm[S_WO + d];
                acc = fmaf(q[1], sm[S_WO + 1 * DD + d], acc);
                acc = fmaf(q[2], sm[S_WO + 2 * DD + d], acc);
                acc = fmaf(q[3], sm[S_WO + 3 * DD + d], acc);
                acc = fmaf(q[4], sm[S_WO + 4 * DD + d], acc);
                acc = fmaf(q[5], sm[S_WO + 5 * DD + d], acc);
                acc = fmaf(q[6], sm[S_WO + 6 * DD + d], acc);
                acc = fmaf(q[7], sm[S_WO + 7 * DD + d], acc);
                acc += sm[S_BOUT + d];
                rp[d * RSTRIDE] -= acc;
            }
        }
    }
    __syncthreads();

    // ---- epilogue: z_q = z - residual_final ----
    for (int idx = tid; idx < DD * TILE; idx += THREADS) {
        int d = idx >> 6, to = idx & 63;
        size_t g = ((size_t)(b * DD + d)) * TT + t0 + to;
        out[ZQ_OFF + g] = z[g] - sm[S_R + d * RSTRIDE + to];
    }

    // ---- loss: deterministic in-block sum, one atomic per CTA ----
    double* lb = reinterpret_cast<double*>(sm + S_LOSS);
    if (tid < 64) lb[tid] = lossAcc;
    __syncthreads();
    if (tid == 0) {
        double s = 0.0;
        for (int j = 0; j < 64; j++) s += lb[j];
        atomicAdd(&g_loss, s);
    }
}

// ---------------- finalize: write scalar losses ----------------
__global__ void rvq_fin(float* __restrict__ out) {
    float v = (float)(g_loss * (1.0 / 524288.0));   // / (B*CDIM*T)
    out[LOSS_OFF]     = v;   // commitment_loss
    out[LOSS_OFF + 1] = v;   // codebook_loss (bitwise equal in forward)
}

// ---------------- launch ----------------
extern "C" void kernel_launch(void* const* d_in, const int* in_sizes, int n_in,
                              void* d_out, int out_size) {
    const float* z     = (const float*)d_in[0];
    const float* w_in  = (const float*)d_in[1];
    const float* b_in  = (const float*)d_in[2];
    const float* w_out = (const float*)d_in[3];
    const float* b_out = (const float*)d_in[4];
    const float* cb    = (const float*)d_in[5];
    float* out = (float*)d_out;

    cudaFuncSetAttribute(rvq_main, cudaFuncAttributeMaxDynamicSharedMemorySize, SMEM_BYTES);

    rvq_prep<<<(NCB * KK + 255) / 256, 256>>>(cb);
    rvq_main<<<(BB * TT) / TILE, THREADS, SMEM_BYTES>>>(z, w_in, b_in, w_out, b_out, cb, out);
    rvq_fin<<<1, 1>>>(out);
}

// round 3
// speedup vs baseline: 1.5649x; 1.5649x over previous
#include <cuda_runtime.h>

// ---------------- problem constants ----------------
#define NCB   9
#define BB    16
#define DD    512
#define TT    4096
#define KK    1024
#define CDIM  8

#define TILE     64
#define THREADS  512

// output layout (float32, concatenated)
#define ZQ_OFF     0ll
#define CODES_OFF  33554432ll
#define LAT_OFF    34144256ll
#define LOSS_OFF   38862848ll

// ---------------- smem layout (float offsets) ----------------
#define S_R     0          // r[d][p]   512*64 = 32768
#define S_WI    32768      // packed [d][c] 4096 (16B aligned)
#define S_WO    36864      // [c][d] 4096
#define S_CBT   40960      // [c][k] 8*1024 = 8192
#define S_C2    49152      // 1024
#define S_BOUT  50176      // 512
#define S_BIN   50688      // 8
#define S_ZE    50696      // [c][p] 512
#define S_EN    51208      // [c][p] 512
#define S_EN2   51720      // 64
#define S_PART  51784      // 64*65 = 4160 (A partials; reused as BESTD/BESTI in B)
#define S_BESTD S_PART
#define S_BESTI (S_PART+512)
#define S_CBQ   55944      // [p*9+c] 576
#define S_LOSS  56520      // 64 doubles = 128 floats (8B aligned)
#define SMEM_FLOATS 56648
#define SMEM_BYTES  (SMEM_FLOATS*4)   // 226592

// ---------------- device scratch ----------------
__device__ float  g_wi_p[NCB * DD * CDIM];   // [i][d][c]
__device__ float  g_wo_t[NCB * CDIM * DD];   // [i][c][d]
__device__ float  g_cbt [NCB * CDIM * KK];   // [i][c][k] (normalized, transposed)
__device__ float  g_c2  [NCB * KK];
__device__ double g_loss;

// ---------------- packed f32x2 helpers ----------------
typedef unsigned long long u64;
__device__ __forceinline__ u64 pk2(float lo, float hi) {
    u64 r; asm("mov.b64 %0,{%1,%2};" : "=l"(r) : "f"(lo), "f"(hi)); return r;
}
__device__ __forceinline__ void upk2(float& lo, float& hi, u64 v) {
    asm("mov.b64 {%0,%1},%2;" : "=f"(lo), "=f"(hi) : "l"(v));
}
__device__ __forceinline__ u64 f2fma(u64 a, u64 b, u64 c) {
    u64 d; asm("fma.rn.f32x2 %0,%1,%2,%3;" : "=l"(d) : "l"(a), "l"(b), "l"(c)); return d;
}
__device__ __forceinline__ u64 f2mul(u64 a, u64 b) {
    u64 d; asm("mul.rn.f32x2 %0,%1,%2;" : "=l"(d) : "l"(a), "l"(b)); return d;
}
__device__ __forceinline__ u64 f2add(u64 a, u64 b) {
    u64 d; asm("add.rn.f32x2 %0,%1,%2;" : "=l"(d) : "l"(a), "l"(b)); return d;
}
__device__ __forceinline__ void cp16(unsigned smaddr, const float* g) {
    asm volatile("cp.async.cg.shared.global [%0], [%1], 16;" :: "r"(smaddr), "l"(g));
}
#define CP_COMMIT() asm volatile("cp.async.commit_group;")
#define CP_WAIT(n)  asm volatile("cp.async.wait_group %0;" :: "n"(n))

// ---------------- prep: normalize + transpose, zero loss ----------------
__global__ void rvq_prep(const float* __restrict__ cb,
                         const float* __restrict__ w_in,
                         const float* __restrict__ w_out) {
    int v = blockIdx.x * blockDim.x + threadIdx.x;
    if (v == 0) g_loss = 0.0;
    if (v < NCB * KK) {
        int i = v / KK, k = v % KK;
        const float* src = cb + (size_t)v * CDIM;
        float x[CDIM];
#pragma unroll
        for (int c = 0; c < CDIM; c++) x[c] = src[c];
        float ss = 0.f;
#pragma unroll
        for (int c = 0; c < CDIM; c++) ss = fmaf(x[c], x[c], ss);
        float den = fmaxf(__fsqrt_rn(ss), 1e-12f);
        float c2 = 0.f;
#pragma unroll
        for (int c = 0; c < CDIM; c++) {
            float e = __fdiv_rn(x[c], den);   // exact IEEE div, matches reference
            g_cbt[((size_t)i * CDIM + c) * KK + k] = e;
            c2 = fmaf(e, e, c2);
        }
        g_c2[v] = c2;
    }
    // weight repack: w_in[i][c][d] -> g_wi_p[i][d][c]; w_out[i][d][c] -> g_wo_t[i][c][d]
    for (int idx = v; idx < NCB * DD * CDIM; idx += gridDim.x * blockDim.x) {
        int i = idx / (DD * CDIM), rem = idx % (DD * CDIM);
        int c = rem / DD, d = rem % DD;
        g_wi_p[(size_t)i * DD * CDIM + d * CDIM + c] = w_in[idx];       // idx=[i][c][d]
        int d2 = rem / CDIM, c2i = rem % CDIM;
        g_wo_t[(size_t)i * CDIM * DD + c2i * DD + d2] = w_out[idx];     // idx=[i][d][c]
    }
}

// ---------------- main fused kernel ----------------
extern __shared__ float sm[];

__global__ void __launch_bounds__(THREADS, 1)
rvq_main(const float* __restrict__ z,
         const float* __restrict__ b_in,
         const float* __restrict__ b_out,
         const float* __restrict__ cbraw,
         float* __restrict__ out) {
    const int tid  = threadIdx.x;
    const int pos0 = blockIdx.x * TILE;
    const int b    = pos0 >> 12;
    const int t0   = pos0 & (TT - 1);
    const unsigned smb = (unsigned)__cvta_generic_to_shared(sm);

    const float* zb = z + ((size_t)b * DD) * TT + t0;

    // stage residual r[d][p]
    for (int idx = tid; idx < DD * TILE; idx += THREADS) {
        int d = idx >> 6, p = idx & 63;
        sm[S_R + d * 64 + p] = zb[(size_t)d * TT + p];
    }

    const int p  = tid & 63;
    const int sl = tid >> 6;
    double lossAcc = 0.0;

    for (int i = 0; i < NCB; ++i) {
        __syncthreads();   // prev iter fully done; r staged

        // ---- stage weights via cp.async (3 groups) ----
        if (tid < CDIM) sm[S_BIN + tid] = b_in[(size_t)i * CDIM + tid];
        {
            const float* wi = g_wi_p + (size_t)i * DD * CDIM;
            cp16(smb + (S_WI + tid * 4) * 4,        wi + tid * 4);
            cp16(smb + (S_WI + 2048 + tid * 4) * 4, wi + 2048 + tid * 4);
        }
        CP_COMMIT();   // group: wi
        {
            const float* ct = g_cbt + (size_t)i * CDIM * KK;
#pragma unroll
            for (int r4 = 0; r4 < 4; r4++)
                cp16(smb + (S_CBT + r4 * 2048 + tid * 4) * 4, ct + r4 * 2048 + tid * 4);
            if (tid < 256) cp16(smb + (S_C2 + tid * 4) * 4, g_c2 + (size_t)i * KK + tid * 4);
        }
        CP_COMMIT();   // group: cbt + c2
        {
            const float* wo = g_wo_t + (size_t)i * CDIM * DD;
            cp16(smb + (S_WO + tid * 4) * 4,        wo + tid * 4);
            cp16(smb + (S_WO + 2048 + tid * 4) * 4, wo + 2048 + tid * 4);
            if (tid < 128) cp16(smb + (S_BOUT + tid * 4) * 4, b_out + (size_t)i * DD + tid * 4);
        }
        CP_COMMIT();   // group: wo + bout

        CP_WAIT(2);    // wi ready
        __syncthreads();

        // ---- Phase A: partial z_e over this thread's 64-d chunk (packed) ----
        {
            const int d0 = sl << 6;
            u64 a01 = 0, a23 = 0, a45 = 0, a67 = 0;
            const float* rp = sm + S_R + p;
#pragma unroll 8
            for (int d = d0; d < d0 + 64; ++d) {
                float rv = rp[d * 64];
                u64 rr = pk2(rv, rv);
                ulonglong2 wA = *reinterpret_cast<const ulonglong2*>(sm + S_WI + d * 8);
                ulonglong2 wB = *reinterpret_cast<const ulonglong2*>(sm + S_WI + d * 8 + 4);
                a01 = f2fma(wA.x, rr, a01);
                a23 = f2fma(wA.y, rr, a23);
                a45 = f2fma(wB.x, rr, a45);
                a67 = f2fma(wB.y, rr, a67);
            }
            float v0,v1,v2,v3,v4,v5,v6,v7;
            upk2(v0,v1,a01); upk2(v2,v3,a23); upk2(v4,v5,a45); upk2(v6,v7,a67);
            float* pb = sm + S_PART + p * 65 + sl;
            pb[0]=v0; pb[8]=v1; pb[16]=v2; pb[24]=v3;
            pb[32]=v4; pb[40]=v5; pb[48]=v6; pb[56]=v7;
        }
        __syncthreads();

        // ---- combineA: z_e[c][p] = sum of 8 partials + b_in[c] ----
        {
            const float* pb = sm + S_PART + p * 65 + sl * 8;
            float s = pb[0];
#pragma unroll
            for (int s8 = 1; s8 < 8; s8++) s += pb[s8];
            sm[S_ZE + sl * 64 + p] = s + sm[S_BIN + sl];
        }
        __syncthreads();

        // ---- normalize (tid<64): en, en2 ----
        if (tid < 64) {
            float zv[8];
#pragma unroll
            for (int c = 0; c < 8; c++) zv[c] = sm[S_ZE + c * 64 + tid];
            float ss = 0.f;
#pragma unroll
            for (int c = 0; c < 8; c++) ss = fmaf(zv[c], zv[c], ss);
            float den = fmaxf(__fsqrt_rn(ss), 1e-12f);
            float e[8], en2 = 0.f;
#pragma unroll
            for (int c = 0; c < 8; c++) { e[c] = __fdiv_rn(zv[c], den); sm[S_EN + c * 64 + tid] = e[c]; }
#pragma unroll
            for (int c = 0; c < 8; c++) en2 = fmaf(e[c], e[c], en2);
            sm[S_EN2 + tid] = en2;
        }
        CP_WAIT(1);   // cbt + c2 ready
        __syncthreads();

        // ---- Phase B: argmin over 128 codes in this slice (packed, 4 codes/iter) ----
        {
            u64 ee[8];
#pragma unroll
            for (int c = 0; c < 8; c++) { float e = sm[S_EN + c * 64 + p]; ee[c] = pk2(e, e); }
            float en2 = sm[S_EN2 + p];
            u64 e2s = pk2(en2, en2);
            u64 m2s = pk2(-2.f, -2.f);

            const int k0 = sl << 7;
            float best = 3.402823466e38f;
            int   bi   = k0;
#pragma unroll 8
            for (int q = 0; q < 32; ++q) {
                const int kb = k0 + (q << 2);
                ulonglong2 c0 = *reinterpret_cast<const ulonglong2*>(sm + S_CBT + 0*KK + kb);
                ulonglong2 c1 = *reinterpret_cast<const ulonglong2*>(sm + S_CBT + 1*KK + kb);
                ulonglong2 c2r= *reinterpret_cast<const ulonglong2*>(sm + S_CBT + 2*KK + kb);
                ulonglong2 c3 = *reinterpret_cast<const ulonglong2*>(sm + S_CBT + 3*KK + kb);
                ulonglong2 c4 = *reinterpret_cast<const ulonglong2*>(sm + S_CBT + 4*KK + kb);
                ulonglong2 c5 = *reinterpret_cast<const ulonglong2*>(sm + S_CBT + 5*KK + kb);
                ulonglong2 c6 = *reinterpret_cast<const ulonglong2*>(sm + S_CBT + 6*KK + kb);
                ulonglong2 c7 = *reinterpret_cast<const ulonglong2*>(sm + S_CBT + 7*KK + kb);
                u64 dA = f2mul(ee[0], c0.x);
                dA = f2fma(ee[1], c1.x, dA); dA = f2fma(ee[2], c2r.x, dA);
                dA = f2fma(ee[3], c3.x, dA); dA = f2fma(ee[4], c4.x, dA);
                dA = f2fma(ee[5], c5.x, dA); dA = f2fma(ee[6], c6.x, dA);
                dA = f2fma(ee[7], c7.x, dA);
                u64 dB = f2mul(ee[0], c0.y);
                dB = f2fma(ee[1], c1.y, dB); dB = f2fma(ee[2], c2r.y, dB);
                dB = f2fma(ee[3], c3.y, dB); dB = f2fma(ee[4], c4.y, dB);
                dB = f2fma(ee[5], c5.y, dB); dB = f2fma(ee[6], c6.y, dB);
                dB = f2fma(ee[7], c7.y, dB);
                ulonglong2 c2p = *reinterpret_cast<const ulonglong2*>(sm + S_C2 + kb);
                u64 distA = f2add(f2fma(m2s, dA, e2s), c2p.x);   // (en2-2dot)+c2, per-lane exact
                u64 distB = f2add(f2fma(m2s, dB, e2s), c2p.y);
                float f0,f1,f2,f3;
                upk2(f0,f1,distA); upk2(f2,f3,distB);
                if (f0 < best) { best = f0; bi = kb;     }
                if (f1 < best) { best = f1; bi = kb + 1; }
                if (f2 < best) { best = f2; bi = kb + 2; }
                if (f3 < best) { best = f3; bi = kb + 3; }
            }
            sm[S_BESTD + (sl << 6) + p] = best;
            reinterpret_cast<int*>(sm + S_BESTI)[(sl << 6) + p] = bi;
        }
        __syncthreads();

        // ---- combineB: latents, codes, gather raw codebook, loss ----
        out[LAT_OFF + ((size_t)(b * (NCB*CDIM) + i*CDIM + sl)) * TT + t0 + p] =
            sm[S_ZE + sl * 64 + p];
        if (tid < 64) {
            float bestd = sm[S_BESTD + tid];
            int   bi    = reinterpret_cast<int*>(sm + S_BESTI)[tid];
#pragma unroll
            for (int s = 1; s < 8; s++) {
                float d2 = sm[S_BESTD + (s << 6) + tid];
                int   i2 = reinterpret_cast<int*>(sm + S_BESTI)[(s << 6) + tid];
                if (d2 < bestd) { bestd = d2; bi = i2; }
            }
            out[CODES_OFF + ((size_t)(b * NCB + i)) * TT + t0 + tid] = (float)bi;
            const float* cr = cbraw + ((size_t)i * KK + bi) * CDIM;
            double ls = 0.0;
#pragma unroll
            for (int cc = 0; cc < 8; cc++) {
                float cv = __ldg(cr + cc);
                sm[S_CBQ + tid * 9 + cc] = cv;
                float df = sm[S_ZE + cc * 64 + tid] - cv;
                ls += (double)(df * df);
            }
            lossAcc += ls;
        }
        CP_WAIT(0);   // wo + bout ready
        __syncthreads();

        // ---- Phase C: r[:,p] -= w_out @ q[p] + b_out (packed over d) ----
        {
            u64 qq[8];
#pragma unroll
            for (int c = 0; c < 8; c++) { float qv = sm[S_CBQ + p * 9 + c]; qq[c] = pk2(qv, qv); }
            const int d0 = sl << 6;
            float* rp = sm + S_R + p;
#pragma unroll 4
            for (int d = d0; d < d0 + 64; d += 4) {
                ulonglong2 w0 = *reinterpret_cast<const ulonglong2*>(sm + S_WO + 0*DD + d);
                ulonglong2 w1 = *reinterpret_cast<const ulonglong2*>(sm + S_WO + 1*DD + d);
                ulonglong2 w2 = *reinterpret_cast<const ulonglong2*>(sm + S_WO + 2*DD + d);
                ulonglong2 w3 = *reinterpret_cast<const ulonglong2*>(sm + S_WO + 3*DD + d);
                ulonglong2 w4 = *reinterpret_cast<const ulonglong2*>(sm + S_WO + 4*DD + d);
                ulonglong2 w5 = *reinterpret_cast<const ulonglong2*>(sm + S_WO + 5*DD + d);
                ulonglong2 w6 = *reinterpret_cast<const ulonglong2*>(sm + S_WO + 6*DD + d);
                ulonglong2 w7 = *reinterpret_cast<const ulonglong2*>(sm + S_WO + 7*DD + d);
                u64 aA = f2mul(qq[0], w0.x);
                aA = f2fma(qq[1], w1.x, aA); aA = f2fma(qq[2], w2.x, aA);
                aA = f2fma(qq[3], w3.x, aA); aA = f2fma(qq[4], w4.x, aA);
                aA = f2fma(qq[5], w5.x, aA); aA = f2fma(qq[6], w6.x, aA);
                aA = f2fma(qq[7], w7.x, aA);
                u64 aB = f2mul(qq[0], w0.y);
                aB = f2fma(qq[1], w1.y, aB); aB = f2fma(qq[2], w2.y, aB);
                aB = f2fma(qq[3], w3.y, aB); aB = f2fma(qq[4], w4.y, aB);
                aB = f2fma(qq[5], w5.y, aB); aB = f2fma(qq[6], w6.y, aB);
                aB = f2fma(qq[7], w7.y, aB);
                ulonglong2 bo = *reinterpret_cast<const ulonglong2*>(sm + S_BOUT + d);
                aA = f2add(aA, bo.x);
                aB = f2add(aB, bo.y);
                float a0,a1,a2,a3;
                upk2(a0,a1,aA); upk2(a2,a3,aB);
                rp[(d    ) * 64] -= a0;
                rp[(d + 1) * 64] -= a1;
                rp[(d + 2) * 64] -= a2;
                rp[(d + 3) * 64] -= a3;
            }
        }
    }
    __syncthreads();

    // ---- epilogue: z_q = z - r_final ----
    for (int idx = tid; idx < DD * TILE; idx += THREADS) {
        int d = idx >> 6, pp = idx & 63;
        size_t g = ((size_t)(b * DD + d)) * TT + t0 + pp;
        out[ZQ_OFF + g] = z[g] - sm[S_R + d * 64 + pp];
    }

    // ---- loss: deterministic in-block sum, one atomic ----
    double* lb = reinterpret_cast<double*>(sm + S_LOSS);
    if (tid < 64) lb[tid] = lossAcc;
    __syncthreads();
    if (tid == 0) {
        double s = 0.0;
        for (int j = 0; j < 64; j++) s += lb[j];
        atomicAdd(&g_loss, s);
    }
}

__global__ void rvq_fin(float* __restrict__ out) {
    float v = (float)(g_loss * (1.0 / 524288.0));
    out[LOSS_OFF]     = v;
    out[LOSS_OFF + 1] = v;
}

extern "C" void kernel_launch(void* const* d_in, const int* in_sizes, int n_in,
                              void* d_out, int out_size) {
    const float* z     = (const float*)d_in[0];
    const float* w_in  = (const float*)d_in[1];
    const float* b_in  = (const float*)d_in[2];
    const float* w_out = (const float*)d_in[3];
    const float* b_out = (const float*)d_in[4];
    const float* cb    = (const float*)d_in[5];
    float* out = (float*)d_out;

    cudaFuncSetAttribute(rvq_main, cudaFuncAttributeMaxDynamicSharedMemorySize, SMEM_BYTES);

    rvq_prep<<<40, 256>>>(cb, w_in, w_out);
    rvq_main<<<(BB * TT) / TILE, THREADS, SMEM_BYTES>>>(z, b_in, b_out, cb, out);
    rvq_fin<<<1, 1>>>(out);
}